// round 1
// baseline (speedup 1.0000x reference)
#include <cuda_runtime.h>
#include <cuda_bf16.h>
#include <cstdint>

// DeterministicLattice: ring-stencil fusion + 5-output "GenesisGeometry" engine.
// out[0] = fused + (1/phi) tanh(fused)
// out[1] = tanh(phi*fused)
// out[2] = sigmoid(phi*fused)
// out[3] = sin(fused)*cos(phi*fused)
// out[4] = fused * exp(-|fused|/phi)
// fused = (phi*x[i] + x[i-1] + x[i+1]) / (phi + 2), ring on axis 0.

#define PHI_F      1.6180339887498949f
#define INVPHI_F   0.6180339887498949f
#define INV_PHI2_F 0.2763932022500210f  // 1/(PHI+2)

__device__ __forceinline__ void genesis_engine(float f,
                                               float& idn, float& bl,
                                               float& cr,  float& tr,
                                               float& sp)
{
    // tanh(f) via one EX2 + one RCP
    float e2 = __expf(f + f);                       // e^{2f}
    float t  = __fdividef(e2 - 1.0f, e2 + 1.0f);    // tanh(f)
    idn = fmaf(INVPHI_F, t, f);                     // identity_next

    // share E = e^{phi f} between bloom (tanh) and crown (sigmoid)
    float E  = __expf(PHI_F * f);
    float E2 = E * E;                               // e^{2 phi f}
    bl = __fdividef(E2 - 1.0f, E2 + 1.0f);          // tanh(phi f)
    cr = __fdividef(E, E + 1.0f);                   // sigmoid(phi f)

    tr = __sinf(f) * __cosf(PHI_F * f);             // triad
    sp = f * __expf(-fabsf(f) * INVPHI_F);          // spiral
}

__global__ void __launch_bounds__(256)
DeterministicLattice_43508018709032_kernel(const float* __restrict__ x,
                                           float* __restrict__ out,
                                           int nrows, int vec_per_row /*=128*/)
{
    const int total4 = nrows * vec_per_row;          // 8,388,608 for nominal shape
    int idx = blockIdx.x * blockDim.x + threadIdx.x;
    if (idx >= total4) return;

    const int row  = idx / vec_per_row;
    const int col  = idx - row * vec_per_row;
    const int mask = nrows - 1;                      // nrows is a power of two (65536)
    const int lrow = (row - 1) & mask;
    const int rrow = (row + 1) & mask;

    const float4* __restrict__ xv = reinterpret_cast<const float4*>(x);
    float4 s = xv[idx];
    float4 l = xv[lrow * vec_per_row + col];
    float4 r = xv[rrow * vec_per_row + col];

    float fs[4] = { s.x, s.y, s.z, s.w };
    float fl[4] = { l.x, l.y, l.z, l.w };
    float fr[4] = { r.x, r.y, r.z, r.w };

    float4 o_idn, o_bl, o_cr, o_tr, o_sp;
    float* pi = &o_idn.x; float* pb = &o_bl.x; float* pc = &o_cr.x;
    float* pt = &o_tr.x;  float* ps = &o_sp.x;

#pragma unroll
    for (int k = 0; k < 4; ++k) {
        // fused = (phi*x + l + r) / (phi + 2)
        float f = (fmaf(PHI_F, fs[k], fl[k]) + fr[k]) * INV_PHI2_F;
        genesis_engine(f, pi[k], pb[k], pc[k], pt[k], ps[k]);
    }

    float4* __restrict__ ov = reinterpret_cast<float4*>(out);
    ov[0 * total4 + idx] = o_idn;   // identity_next
    ov[1 * total4 + idx] = o_bl;    // bloom
    ov[2 * total4 + idx] = o_cr;    // crown
    ov[3 * total4 + idx] = o_tr;    // triad
    ov[4 * total4 + idx] = o_sp;    // spiral
}

extern "C" void kernel_launch(void* const* d_in, const int* in_sizes, int n_in,
                              void* d_out, int out_size)
{
    const float* x = (const float*)d_in[0];
    float* out = (float*)d_out;

    const int DIM   = 512;
    const int nrows = in_sizes[0] / DIM;             // 65536
    const int vec_per_row = DIM / 4;                 // 128
    const int total4 = nrows * vec_per_row;          // 8,388,608

    const int threads = 256;
    const int blocks  = (total4 + threads - 1) / threads;
    DeterministicLattice_43508018709032_kernel<<<blocks, threads>>>(x, out, nrows, vec_per_row);
}